// round 3
// baseline (speedup 1.0000x reference)
#include <cuda_runtime.h>
#include <cstdint>

// ---------------------------------------------------------------------------
// Differential attention: B=4, S=1024, E=1024, H=16, HD=64, HD2=32
// Output = concat( out[B,S,E] , diff_w[B,H,S,S] )  (fp32)
// ---------------------------------------------------------------------------

#define LAMBDA_INIT  0.777870099559256f
#define ONE_MINUS_LI 0.222129900440744f

__device__ float g_Q[4096 * 1024];
__device__ float g_K[4096 * 1024];
__device__ float g_V[4096 * 1024];
__device__ float g_A[4096 * 1024];

// ---------------------------------------------------------------------------
// C[4096,1024] = A[4096,1024] @ W[1024,1024]^T + bias   (128x128x8 tiles)
// ---------------------------------------------------------------------------
__global__ __launch_bounds__(256) void sgemm_nt(const float* __restrict__ A,
                                                const float* __restrict__ W,
                                                const float* __restrict__ bias,
                                                float* __restrict__ C) {
  constexpr int K = 1024, N = 1024;
  __shared__ float As[8][132];
  __shared__ float Bs[8][132];
  const int tid = threadIdx.x;
  const int tx = tid & 15, ty = tid >> 4;
  const int m0 = blockIdx.y << 7, n0 = blockIdx.x << 7;
  const int lr = tid >> 1;
  const int lk = (tid & 1) << 2;
  const float* Ag = A + (m0 + lr) * K + lk;
  const float* Wg = W + (n0 + lr) * K + lk;

  float acc[8][8];
#pragma unroll
  for (int i = 0; i < 8; i++)
#pragma unroll
    for (int j = 0; j < 8; j++) acc[i][j] = 0.0f;

  float4 av = *(const float4*)Ag;
  float4 bv = *(const float4*)Wg;

  for (int k0 = 0; k0 < K; k0 += 8) {
    As[lk + 0][lr] = av.x; As[lk + 1][lr] = av.y;
    As[lk + 2][lr] = av.z; As[lk + 3][lr] = av.w;
    Bs[lk + 0][lr] = bv.x; Bs[lk + 1][lr] = bv.y;
    Bs[lk + 2][lr] = bv.z; Bs[lk + 3][lr] = bv.w;
    __syncthreads();
    if (k0 + 8 < K) {
      av = *(const float4*)(Ag + k0 + 8);
      bv = *(const float4*)(Wg + k0 + 8);
    }
#pragma unroll
    for (int kk = 0; kk < 8; kk++) {
      float a[8], b[8];
      *(float4*)(a + 0) = *(const float4*)&As[kk][ty * 8];
      *(float4*)(a + 4) = *(const float4*)&As[kk][ty * 8 + 4];
      *(float4*)(b + 0) = *(const float4*)&Bs[kk][tx * 8];
      *(float4*)(b + 4) = *(const float4*)&Bs[kk][tx * 8 + 4];
#pragma unroll
      for (int i = 0; i < 8; i++)
#pragma unroll
        for (int j = 0; j < 8; j++) acc[i][j] += a[i] * b[j];
    }
    __syncthreads();
  }

#pragma unroll
  for (int i = 0; i < 8; i++) {
    const int row = m0 + ty * 8 + i;
#pragma unroll
    for (int j = 0; j < 8; j += 4) {
      const int col = n0 + tx * 8 + j;
      float4 o;
      o.x = acc[i][j + 0] + bias[col + 0];
      o.y = acc[i][j + 1] + bias[col + 1];
      o.z = acc[i][j + 2] + bias[col + 2];
      o.w = acc[i][j + 3] + bias[col + 3];
      *(float4*)&C[row * N + col] = o;
    }
  }
}

// ---------------------------------------------------------------------------
// attn_scores: one CTA per (b, h, 16 queries). Both sub-head score rows
// (2 x 16 x 1024 fp32) live in smem; exact softmax; diff -> diff_out.
// Dynamic smem layout (floats):
//   sc  : [2][16][1028]          offset 0      size 32896
//   qs  : [64][16]               offset 32896  size 1024
//   kt  : [64][68]               offset 33920  size 4352
//   inv : [32]                   offset 38272
//   lam : [1]                    offset 38304
// ---------------------------------------------------------------------------
#define SC_STRIDE 1028
#define SC_SUB    (16 * SC_STRIDE)
#define QS_OFF    32896
#define KT_OFF    33920
#define INV_OFF   38272
#define LAM_OFF   38304
#define SMEM_SC_BYTES ((LAM_OFF + 8) * 4)

__global__ __launch_bounds__(256) void attn_scores(
    const float* __restrict__ lq1, const float* __restrict__ lk1,
    const float* __restrict__ lq2, const float* __restrict__ lk2,
    float* __restrict__ diff_out) {
  extern __shared__ float sm[];
  float* sc  = sm;
  float* qs  = sm + QS_OFF;
  float* kt  = sm + KT_OFF;
  float* inv = sm + INV_OFF;

  const int tid = threadIdx.x;
  const int qb = blockIdx.x;     // 0..63 (16 queries each)
  const int h  = blockIdx.y;     // 0..15
  const int b  = blockIdx.z;     // 0..3
  const int bs0  = b << 10;
  const int col0 = h << 6;

  if (tid < 32) {                // lambda
    float a = lq1[tid] * lk1[tid];
    float c = lq2[tid] * lk2[tid];
#pragma unroll
    for (int o = 16; o; o >>= 1) {
      a += __shfl_xor_sync(0xffffffffu, a, o);
      c += __shfl_xor_sync(0xffffffffu, c, o);
    }
    if (tid == 0) sm[LAM_OFF] = expf(a) - expf(c) + LAMBDA_INIT;
  }

  // load 16 query rows (64 dims = both sub-heads), pre-scaled by 1/sqrt(64)
#pragma unroll
  for (int i = 0; i < 4; i++) {
    int idx = i * 256 + tid;
    int qi = idx >> 6, d = idx & 63;
    qs[d * 16 + qi] = g_Q[(bs0 + (qb << 4) + qi) * 1024 + col0 + d] * 0.125f;
  }

  const int q  = tid & 15;
  const int k0 = (tid >> 4) << 2;

  for (int t = 0; t < 16; t++) {       // 16 key tiles of 64
    __syncthreads();
#pragma unroll
    for (int i = 0; i < 4; i++) {      // stage K tile transposed: kt[d][key]
      int f = i * 256 + tid;
      int key = f >> 4, d4 = (f & 15) << 2;
      float4 v = *(const float4*)&g_K[(bs0 + t * 64 + key) * 1024 + col0 + d4];
      kt[(d4 + 0) * 68 + key] = v.x;
      kt[(d4 + 1) * 68 + key] = v.y;
      kt[(d4 + 2) * 68 + key] = v.z;
      kt[(d4 + 3) * 68 + key] = v.w;
    }
    __syncthreads();

    float a1[4] = {0.f, 0.f, 0.f, 0.f};
    float a2[4] = {0.f, 0.f, 0.f, 0.f};
#pragma unroll
    for (int d = 0; d < 32; d++) {
      float qv = qs[d * 16 + q];
      float4 kv = *(const float4*)&kt[d * 68 + k0];
      a1[0] += qv * kv.x; a1[1] += qv * kv.y;
      a1[2] += qv * kv.z; a1[3] += qv * kv.w;
    }
#pragma unroll
    for (int d = 32; d < 64; d++) {
      float qv = qs[d * 16 + q];
      float4 kv = *(const float4*)&kt[d * 68 + k0];
      a2[0] += qv * kv.x; a2[1] += qv * kv.y;
      a2[2] += qv * kv.z; a2[3] += qv * kv.w;
    }
    *(float4*)&sc[q * SC_STRIDE + t * 64 + k0] =
        make_float4(a1[0], a1[1], a1[2], a1[3]);
    *(float4*)&sc[SC_SUB + q * SC_STRIDE + t * 64 + k0] =
        make_float4(a2[0], a2[1], a2[2], a2[3]);
  }
  __syncthreads();

  // softmax: 32 rows (2 sub x 16 q), one warp per row (8 warps, 4 rows each)
  const int wid = tid >> 5, lane = tid & 31;
  for (int r = wid; r < 32; r += 8) {
    float* row = sc + (r >> 4) * SC_SUB + (r & 15) * SC_STRIDE;
    float m = -1e30f;
#pragma unroll 4
    for (int k = lane; k < 1024; k += 32) m = fmaxf(m, row[k]);
#pragma unroll
    for (int o = 16; o; o >>= 1) m = fmaxf(m, __shfl_xor_sync(0xffffffffu, m, o));
    float s = 0.f;
#pragma unroll 4
    for (int k = lane; k < 1024; k += 32) {
      float e = __expf(row[k] - m);
      row[k] = e;
      s += e;
    }
#pragma unroll
    for (int o = 16; o; o >>= 1) s += __shfl_xor_sync(0xffffffffu, s, o);
    if (lane == 0) inv[r] = 1.0f / s;
  }
  __syncthreads();

  // diff = p1 - lam*p2, coalesced float4 stores to global
  const float lam = sm[LAM_OFF];
  float* dst = diff_out + ((size_t)(b * 16 + h) * 1024 + (qb << 4)) * 1024;
#pragma unroll 1
  for (int qq = 0; qq < 16; qq++) {
    float i1 = inv[qq], i2 = inv[16 + qq] * lam;
    float4 e1 = *(const float4*)&sc[qq * SC_STRIDE + tid * 4];
    float4 e2 = *(const float4*)&sc[SC_SUB + qq * SC_STRIDE + tid * 4];
    float4 o;
    o.x = e1.x * i1 - e2.x * i2;
    o.y = e1.y * i1 - e2.y * i2;
    o.z = e1.z * i1 - e2.z * i2;
    o.w = e1.w * i1 - e2.w * i2;
    *(float4*)&dst[(size_t)qq * 1024 + tid * 4] = o;
  }
}

// ---------------------------------------------------------------------------
// attn_pv: attn[b,h,q,d] = sum_k diff[b,h,q,k] * V[b,k,h*64+d]
// then RMSNorm over d (64), * subln_w * (1-LI), write g_A[b,q,h*64+d]
// One CTA per (bh, 32 queries).
// ---------------------------------------------------------------------------
__global__ __launch_bounds__(256) void attn_pv(const float* __restrict__ diff,
                                               const float* __restrict__ subln) {
  __shared__ float dt[32 * 68];
  __shared__ float vt[64 * 68];
  const int tid = threadIdx.x;
  const int q0 = blockIdx.x << 5;
  const int bh = blockIdx.y;
  const int b = bh >> 4, h = bh & 15;
  const size_t drow = ((size_t)bh * 1024 + q0) * 1024;

  const int q = tid >> 3;
  const int d0 = (tid & 7) << 3;
  float acc[8] = {0.f, 0.f, 0.f, 0.f, 0.f, 0.f, 0.f, 0.f};

  for (int t = 0; t < 16; t++) {       // key tiles of 64
    __syncthreads();
#pragma unroll
    for (int i = 0; i < 2; i++) {      // diff tile [32q][64k]
      int f = i * 256 + tid;
      int qi = f >> 4, k4 = (f & 15) << 2;
      float4 v = *(const float4*)&diff[drow + (size_t)qi * 1024 + t * 64 + k4];
      dt[qi * 68 + k4 + 0] = v.x; dt[qi * 68 + k4 + 1] = v.y;
      dt[qi * 68 + k4 + 2] = v.z; dt[qi * 68 + k4 + 3] = v.w;
    }
#pragma unroll
    for (int i = 0; i < 4; i++) {      // V tile [64k][64d]
      int f = i * 256 + tid;
      int k = f >> 4, d4 = (f & 15) << 2;
      float4 v = *(const float4*)&g_V[(size_t)(b * 1024 + t * 64 + k) * 1024 + h * 64 + d4];
      vt[k * 68 + d4 + 0] = v.x; vt[k * 68 + d4 + 1] = v.y;
      vt[k * 68 + d4 + 2] = v.z; vt[k * 68 + d4 + 3] = v.w;
    }
    __syncthreads();

#pragma unroll
    for (int k = 0; k < 64; k++) {
      float dv = dt[q * 68 + k];
      float4 va = *(const float4*)&vt[k * 68 + d0];
      float4 vb = *(const float4*)&vt[k * 68 + d0 + 4];
      acc[0] += dv * va.x; acc[1] += dv * va.y;
      acc[2] += dv * va.z; acc[3] += dv * va.w;
      acc[4] += dv * vb.x; acc[5] += dv * vb.y;
      acc[6] += dv * vb.z; acc[7] += dv * vb.w;
    }
  }

  // RMSNorm over 64 dims: reduce sum of squares across 8 lanes of same q
  float ss = 0.f;
#pragma unroll
  for (int j = 0; j < 8; j++) ss += acc[j] * acc[j];
#pragma unroll
  for (int o = 4; o; o >>= 1) ss += __shfl_xor_sync(0xffffffffu, ss, o);
  const float scale = rsqrtf(ss * (1.0f / 64.0f) + 1e-5f) * ONE_MINUS_LI;

  float* dst = &g_A[(size_t)(b * 1024 + q0 + q) * 1024 + h * 64 + d0];
#pragma unroll
  for (int j = 0; j < 8; j++) dst[j] = acc[j] * scale * subln[d0 + j];
}

// ---------------------------------------------------------------------------
extern "C" void kernel_launch(void* const* d_in, const int* in_sizes, int n_in,
                              void* d_out, int out_size) {
  const float* hs  = (const float*)d_in[0];
  const float* q_w = (const float*)d_in[1];
  const float* q_b = (const float*)d_in[2];
  const float* k_w = (const float*)d_in[3];
  const float* k_b = (const float*)d_in[4];
  const float* v_w = (const float*)d_in[5];
  const float* v_b = (const float*)d_in[6];
  const float* o_w = (const float*)d_in[7];
  const float* o_b = (const float*)d_in[8];
  const float* lq1 = (const float*)d_in[9];
  const float* lk1 = (const float*)d_in[10];
  const float* lq2 = (const float*)d_in[11];
  const float* lk2 = (const float*)d_in[12];
  const float* sw  = (const float*)d_in[13];

  float* out  = (float*)d_out;
  float* diff = out + 4u * 1024u * 1024u;   // diff_w region

  float *Q, *K, *V, *A;
  cudaGetSymbolAddress((void**)&Q, g_Q);
  cudaGetSymbolAddress((void**)&K, g_K);
  cudaGetSymbolAddress((void**)&V, g_V);
  cudaGetSymbolAddress((void**)&A, g_A);

  cudaFuncSetAttribute(attn_scores, cudaFuncAttributeMaxDynamicSharedMemorySize,
                       SMEM_SC_BYTES);

  dim3 gGemm(8, 32);
  sgemm_nt<<<gGemm, 256>>>(hs, q_w, q_b, Q);
  sgemm_nt<<<gGemm, 256>>>(hs, k_w, k_b, K);
  sgemm_nt<<<gGemm, 256>>>(hs, v_w, v_b, V);

  dim3 gSc(64, 16, 4);
  attn_scores<<<gSc, 256, SMEM_SC_BYTES>>>(lq1, lk1, lq2, lk2, diff);

  dim3 gPv(32, 64);
  attn_pv<<<gPv, 256>>>(diff, sw);

  sgemm_nt<<<gGemm, 256>>>(A, o_w, o_b, out);
}

// round 5
// speedup vs baseline: 1.4919x; 1.4919x over previous
#include <cuda_runtime.h>
#include <cstdint>

// Differential attention: B=4, S=1024, E=1024, H=16, HD=64, HD2=32
// Output = concat( out[B,S,E] , diff_w[B,H,S,S] )  (fp32)

#define LAMBDA_INIT  0.777870099559256f
#define ONE_MINUS_LI 0.222129900440744f

__device__ float g_Q[4096 * 1024];
__device__ float g_K[4096 * 1024];
__device__ float g_V[4096 * 1024];
__device__ float g_A[4096 * 1024];

// bank swizzle: multiple of 4, < 32 -> float4 alignment preserved
#define SWZ(r) ((((r) >> 1) & 7) << 2)

// ---------------------------------------------------------------------------
// C[4096,1024] = A @ W^T + bias   (128x128x8 tiles)
// ---------------------------------------------------------------------------
__global__ __launch_bounds__(256) void sgemm_nt(const float* __restrict__ A,
                                                const float* __restrict__ W,
                                                const float* __restrict__ bias,
                                                float* __restrict__ C) {
  constexpr int K = 1024, N = 1024;
  __shared__ float As[8][132];
  __shared__ float Bs[8][132];
  const int tid = threadIdx.x;
  const int tx = tid & 15, ty = tid >> 4;
  const int m0 = blockIdx.y << 7, n0 = blockIdx.x << 7;
  const int lr = tid >> 1;
  const int lk = (tid & 1) << 2;
  const float* Ag = A + (m0 + lr) * K + lk;
  const float* Wg = W + (n0 + lr) * K + lk;

  float acc[8][8];
#pragma unroll
  for (int i = 0; i < 8; i++)
#pragma unroll
    for (int j = 0; j < 8; j++) acc[i][j] = 0.0f;

  float4 av = *(const float4*)Ag;
  float4 bv = *(const float4*)Wg;

  for (int k0 = 0; k0 < K; k0 += 8) {
    As[lk + 0][lr] = av.x; As[lk + 1][lr] = av.y;
    As[lk + 2][lr] = av.z; As[lk + 3][lr] = av.w;
    Bs[lk + 0][lr] = bv.x; Bs[lk + 1][lr] = bv.y;
    Bs[lk + 2][lr] = bv.z; Bs[lk + 3][lr] = bv.w;
    __syncthreads();
    if (k0 + 8 < K) {
      av = *(const float4*)(Ag + k0 + 8);
      bv = *(const float4*)(Wg + k0 + 8);
    }
#pragma unroll
    for (int kk = 0; kk < 8; kk++) {
      float a[8], b[8];
      *(float4*)(a + 0) = *(const float4*)&As[kk][ty * 8];
      *(float4*)(a + 4) = *(const float4*)&As[kk][ty * 8 + 4];
      *(float4*)(b + 0) = *(const float4*)&Bs[kk][tx * 8];
      *(float4*)(b + 4) = *(const float4*)&Bs[kk][tx * 8 + 4];
#pragma unroll
      for (int i = 0; i < 8; i++)
#pragma unroll
        for (int j = 0; j < 8; j++) acc[i][j] += a[i] * b[j];
    }
    __syncthreads();
  }

#pragma unroll
  for (int i = 0; i < 8; i++) {
    const int row = m0 + ty * 8 + i;
#pragma unroll
    for (int j = 0; j < 8; j += 4) {
      const int col = n0 + tx * 8 + j;
      float4 o;
      o.x = acc[i][j + 0] + bias[col + 0];
      o.y = acc[i][j + 1] + bias[col + 1];
      o.z = acc[i][j + 2] + bias[col + 2];
      o.w = acc[i][j + 3] + bias[col + 3];
      *(float4*)&C[row * N + col] = o;
    }
  }
}

// ---------------------------------------------------------------------------
// attn_scores: CTA = (b, h, 16 queries). 2q x 8k per thread.
// smem floats: sc[2][16][1028] | qs[64][16] | kt[64][260] swizzled | inv | lam
// ---------------------------------------------------------------------------
#define SC_STRIDE 1028
#define SC_SUB    (16 * SC_STRIDE)
#define QS_OFF    (2 * SC_SUB)             /* 32896 */
#define KT_OFF    (QS_OFF + 1024)          /* 33920 */
#define KT_S      260
#define INV_OFF   (KT_OFF + 64 * KT_S)     /* 50560 */
#define LAM_OFF   (INV_OFF + 32)
#define SMEM_SC_BYTES ((LAM_OFF + 8) * 4)

__global__ __launch_bounds__(256) void attn_scores(
    const float* __restrict__ lq1, const float* __restrict__ lk1,
    const float* __restrict__ lq2, const float* __restrict__ lk2,
    float* __restrict__ diff_out) {
  extern __shared__ float sm[];
  float* sc  = sm;
  float* qs  = sm + QS_OFF;
  float* kt  = sm + KT_OFF;
  float* inv = sm + INV_OFF;

  const int tid = threadIdx.x;
  const int qb = blockIdx.x, h = blockIdx.y, b = blockIdx.z;
  const int bs0  = b << 10;
  const int col0 = h << 6;

  if (tid < 32) {
    float a = lq1[tid] * lk1[tid];
    float c = lq2[tid] * lk2[tid];
#pragma unroll
    for (int o = 16; o; o >>= 1) {
      a += __shfl_xor_sync(0xffffffffu, a, o);
      c += __shfl_xor_sync(0xffffffffu, c, o);
    }
    if (tid == 0) sm[LAM_OFF] = expf(a) - expf(c) + LAMBDA_INIT;
  }

  // 16 query rows, 64 dims, pre-scaled 1/sqrt(64); layout qs[d][q]
#pragma unroll
  for (int i = 0; i < 4; i++) {
    int idx = i * 256 + tid;
    int qi = idx >> 6, d = idx & 63;
    qs[d * 16 + qi] = g_Q[(bs0 + (qb << 4) + qi) * 1024 + col0 + d] * 0.125f;
  }

  const int q0 = (tid >> 5) << 1;      // warp -> 2 queries
  const int kA = (tid & 31) << 2;      // keys [kA,kA+4) and [kA+128,kA+132)

  for (int t = 0; t < 4; t++) {        // 4 key tiles of 256
    __syncthreads();
#pragma unroll
    for (int i = 0; i < 16; i++) {     // stage K tile transposed kt[d][key^SWZ(d)]
      int f = i * 256 + tid;
      int key = f >> 4, d4 = (f & 15) << 2;
      float4 v = *(const float4*)&g_K[(bs0 + t * 256 + key) * 1024 + col0 + d4];
      kt[(d4 + 0) * KT_S + (key ^ SWZ(d4 + 0))] = v.x;
      kt[(d4 + 1) * KT_S + (key ^ SWZ(d4 + 1))] = v.y;
      kt[(d4 + 2) * KT_S + (key ^ SWZ(d4 + 2))] = v.z;
      kt[(d4 + 3) * KT_S + (key ^ SWZ(d4 + 3))] = v.w;
    }
    __syncthreads();

    float a1[2][8] = {}, a2[2][8] = {};
#pragma unroll
    for (int d = 0; d < 32; d++) {
      float2 qv = *(const float2*)&qs[d * 16 + q0];
      float4 ka = *(const float4*)&kt[d * KT_S + (kA ^ SWZ(d))];
      float4 kb = *(const float4*)&kt[d * KT_S + ((kA + 128) ^ SWZ(d))];
      float kk[8] = {ka.x, ka.y, ka.z, ka.w, kb.x, kb.y, kb.z, kb.w};
#pragma unroll
      for (int j = 0; j < 8; j++) {
        a1[0][j] += qv.x * kk[j];
        a1[1][j] += qv.y * kk[j];
      }
    }
#pragma unroll
    for (int d = 32; d < 64; d++) {
      float2 qv = *(const float2*)&qs[d * 16 + q0];
      float4 ka = *(const float4*)&kt[d * KT_S + (kA ^ SWZ(d))];
      float4 kb = *(const float4*)&kt[d * KT_S + ((kA + 128) ^ SWZ(d))];
      float kk[8] = {ka.x, ka.y, ka.z, ka.w, kb.x, kb.y, kb.z, kb.w};
#pragma unroll
      for (int j = 0; j < 8; j++) {
        a2[0][j] += qv.x * kk[j];
        a2[1][j] += qv.y * kk[j];
      }
    }
#pragma unroll
    for (int i = 0; i < 2; i++) {
      float* r1 = sc + (q0 + i) * SC_STRIDE + t * 256;
      float* r2 = r1 + SC_SUB;
      *(float4*)&r1[kA]       = make_float4(a1[i][0], a1[i][1], a1[i][2], a1[i][3]);
      *(float4*)&r1[kA + 128] = make_float4(a1[i][4], a1[i][5], a1[i][6], a1[i][7]);
      *(float4*)&r2[kA]       = make_float4(a2[i][0], a2[i][1], a2[i][2], a2[i][3]);
      *(float4*)&r2[kA + 128] = make_float4(a2[i][4], a2[i][5], a2[i][6], a2[i][7]);
    }
  }
  __syncthreads();

  // softmax: 32 rows, 8 warps x 4 rows
  const int wid = tid >> 5, lane = tid & 31;
  for (int r = wid; r < 32; r += 8) {
    float* row = sc + (r >> 4) * SC_SUB + (r & 15) * SC_STRIDE;
    float m = -1e30f;
#pragma unroll 4
    for (int k = lane; k < 1024; k += 32) m = fmaxf(m, row[k]);
#pragma unroll
    for (int o = 16; o; o >>= 1) m = fmaxf(m, __shfl_xor_sync(0xffffffffu, m, o));
    float s = 0.f;
#pragma unroll 4
    for (int k = lane; k < 1024; k += 32) {
      float e = __expf(row[k] - m);
      row[k] = e;
      s += e;
    }
#pragma unroll
    for (int o = 16; o; o >>= 1) s += __shfl_xor_sync(0xffffffffu, s, o);
    if (lane == 0) inv[r] = 1.0f / s;
  }
  __syncthreads();

  const float lam = sm[LAM_OFF];
  float* dst = diff_out + ((size_t)(b * 16 + h) * 1024 + (qb << 4)) * 1024;
#pragma unroll 1
  for (int qq = 0; qq < 16; qq++) {
    float i1 = inv[qq], i2 = inv[16 + qq] * lam;
    float4 e1 = *(const float4*)&sc[qq * SC_STRIDE + tid * 4];
    float4 e2 = *(const float4*)&sc[SC_SUB + qq * SC_STRIDE + tid * 4];
    float4 o;
    o.x = e1.x * i1 - e2.x * i2;
    o.y = e1.y * i1 - e2.y * i2;
    o.z = e1.z * i1 - e2.z * i2;
    o.w = e1.w * i1 - e2.w * i2;
    *(float4*)&dst[(size_t)qq * 1024 + tid * 4] = o;
  }
}

// ---------------------------------------------------------------------------
// attn_pv: CTA = (bh, 128 queries). 4q x 8d per thread, diff tile transposed.
// smem: dt[64][132] swizzled (k-major), vt[64][68]
// ---------------------------------------------------------------------------
#define DT_S 132
__global__ __launch_bounds__(256) void attn_pv(const float* __restrict__ diff,
                                               const float* __restrict__ subln) {
  __shared__ float dt[64 * DT_S];
  __shared__ float vt[64 * 68];
  const int tid = threadIdx.x;
  const int q0g = blockIdx.x << 7;     // 128-query block
  const int bh = blockIdx.y;
  const int b = bh >> 4, h = bh & 15;
  const size_t drow = ((size_t)bh * 1024 + q0g) * 1024;

  const int d0 = (tid & 7) << 3;       // 8 dims
  const int q0 = (tid >> 3) << 2;      // 4 queries (0..124)
  float acc[4][8] = {};

  for (int t = 0; t < 16; t++) {       // key tiles of 64
    __syncthreads();
#pragma unroll
    for (int i = 0; i < 8; i++) {      // diff tile [128q][64k] -> dt[k][q^SWZ(k)]
      int f = i * 256 + tid;
      int qi = f >> 4, k4 = (f & 15) << 2;
      float4 v = *(const float4*)&diff[drow + (size_t)qi * 1024 + t * 64 + k4];
      dt[(k4 + 0) * DT_S + (qi ^ SWZ(k4 + 0))] = v.x;
      dt[(k4 + 1) * DT_S + (qi ^ SWZ(k4 + 1))] = v.y;
      dt[(k4 + 2) * DT_S + (qi ^ SWZ(k4 + 2))] = v.z;
      dt[(k4 + 3) * DT_S + (qi ^ SWZ(k4 + 3))] = v.w;
    }
#pragma unroll
    for (int i = 0; i < 4; i++) {      // V tile [64k][64d]
      int f = i * 256 + tid;
      int k = f >> 4, d4 = (f & 15) << 2;
      float4 v = *(const float4*)&g_V[(size_t)(b * 1024 + t * 64 + k) * 1024 + h * 64 + d4];
      vt[k * 68 + d4 + 0] = v.x; vt[k * 68 + d4 + 1] = v.y;
      vt[k * 68 + d4 + 2] = v.z; vt[k * 68 + d4 + 3] = v.w;
    }
    __syncthreads();

#pragma unroll
    for (int k = 0; k < 64; k++) {
      float4 qv = *(const float4*)&dt[k * DT_S + (q0 ^ SWZ(k))];
      float4 va = *(const float4*)&vt[k * 68 + d0];
      float4 vb = *(const float4*)&vt[k * 68 + d0 + 4];
      float vv[8] = {va.x, va.y, va.z, va.w, vb.x, vb.y, vb.z, vb.w};
      float qq[4] = {qv.x, qv.y, qv.z, qv.w};
#pragma unroll
      for (int i = 0; i < 4; i++)
#pragma unroll
        for (int j = 0; j < 8; j++) acc[i][j] += qq[i] * vv[j];
    }
  }

  // RMSNorm per query over 64 dims: reduce across 8 d-threads
#pragma unroll
  for (int i = 0; i < 4; i++) {
    float ss = 0.f;
#pragma unroll
    for (int j = 0; j < 8; j++) ss += acc[i][j] * acc[i][j];
#pragma unroll
    for (int o = 4; o; o >>= 1) ss += __shfl_xor_sync(0xffffffffu, ss, o);
    const float scale = rsqrtf(ss * (1.0f / 64.0f) + 1e-5f) * ONE_MINUS_LI;
    float* dst = &g_A[(size_t)(b * 1024 + q0g + q0 + i) * 1024 + h * 64 + d0];
    float4 o1, o2;
    o1.x = acc[i][0] * scale * subln[d0 + 0];
    o1.y = acc[i][1] * scale * subln[d0 + 1];
    o1.z = acc[i][2] * scale * subln[d0 + 2];
    o1.w = acc[i][3] * scale * subln[d0 + 3];
    o2.x = acc[i][4] * scale * subln[d0 + 4];
    o2.y = acc[i][5] * scale * subln[d0 + 5];
    o2.z = acc[i][6] * scale * subln[d0 + 6];
    o2.w = acc[i][7] * scale * subln[d0 + 7];
    *(float4*)&dst[0] = o1;
    *(float4*)&dst[4] = o2;
  }
}

// ---------------------------------------------------------------------------
extern "C" void kernel_launch(void* const* d_in, const int* in_sizes, int n_in,
                              void* d_out, int out_size) {
  const float* hs  = (const float*)d_in[0];
  const float* q_w = (const float*)d_in[1];
  const float* q_b = (const float*)d_in[2];
  const float* k_w = (const float*)d_in[3];
  const float* k_b = (const float*)d_in[4];
  const float* v_w = (const float*)d_in[5];
  const float* v_b = (const float*)d_in[6];
  const float* o_w = (const float*)d_in[7];
  const float* o_b = (const float*)d_in[8];
  const float* lq1 = (const float*)d_in[9];
  const float* lk1 = (const float*)d_in[10];
  const float* lq2 = (const float*)d_in[11];
  const float* lk2 = (const float*)d_in[12];
  const float* sw  = (const float*)d_in[13];

  float* out  = (float*)d_out;
  float* diff = out + 4u * 1024u * 1024u;

  float *Q, *K, *V, *A;
  cudaGetSymbolAddress((void**)&Q, g_Q);
  cudaGetSymbolAddress((void**)&K, g_K);
  cudaGetSymbolAddress((void**)&V, g_V);
  cudaGetSymbolAddress((void**)&A, g_A);

  cudaFuncSetAttribute(attn_scores, cudaFuncAttributeMaxDynamicSharedMemorySize,
                       SMEM_SC_BYTES);

  dim3 gGemm(8, 32);
  sgemm_nt<<<gGemm, 256>>>(hs, q_w, q_b, Q);
  sgemm_nt<<<gGemm, 256>>>(hs, k_w, k_b, K);
  sgemm_nt<<<gGemm, 256>>>(hs, v_w, v_b, V);

  dim3 gSc(64, 16, 4);
  attn_scores<<<gSc, 256, SMEM_SC_BYTES>>>(lq1, lk1, lq2, lk2, diff);

  dim3 gPv(8, 64);
  attn_pv<<<gPv, 256>>>(diff, sw);

  sgemm_nt<<<gGemm, 256>>>(A, o_w, o_b, out);
}